// round 16
// baseline (speedup 1.0000x reference)
#include <cuda_runtime.h>
#include <stdint.h>

#define NB 32768
#define NE 1024

// add on the FMA pipe: d = a*one + b (one==1, opaque runtime value -> IMAD)
static __device__ __forceinline__ uint32_t fadd(uint32_t a, uint32_t b, uint32_t one) {
    uint32_t d;
    asm("mad.lo.u32 %0, %1, %2, %3;" : "=r"(d) : "r"(a), "r"(one), "r"(b));
    return d;
}
#define FADDC(d, a, C) asm("mad.lo.u32 %0, %1, %2, %3;" : "=r"(d) : "r"(a), "r"(one), "n"(C))

static __device__ __forceinline__ uint32_t rotl32(uint32_t x, int r) {
    return __funnelshift_l(x, x, r);
}

// threefry2x32, key (0,42), block (0,i). Returns x0^x1 after 20 rounds —
// matches jax _threefry_random_bits_partitionable (bit_width=32).
// Caller pre-adds ks1=42 into x1. Adds forced to IMAD (fma pipe);
// rotates stay SHF+LOP3 (alu pipe) — empirically the fastest form.
static __device__ __forceinline__ uint32_t tf(uint32_t x1, uint32_t one) {
    uint32_t x0;
    x0 = x1;                 x1 = rotl32(x1, 13) ^ x0;
    x0 = fadd(x0, x1, one);  x1 = rotl32(x1, 15) ^ x0;
    x0 = fadd(x0, x1, one);  x1 = rotl32(x1, 26) ^ x0;
    x0 = fadd(x0, x1, one);  x1 = rotl32(x1,  6) ^ x0;
    FADDC(x0, x0, 42u);  FADDC(x1, x1, 0x1BD11BF0u + 1u);
    x0 = fadd(x0, x1, one);  x1 = rotl32(x1, 17) ^ x0;
    x0 = fadd(x0, x1, one);  x1 = rotl32(x1, 29) ^ x0;
    x0 = fadd(x0, x1, one);  x1 = rotl32(x1, 16) ^ x0;
    x0 = fadd(x0, x1, one);  x1 = rotl32(x1, 24) ^ x0;
    FADDC(x0, x0, 0x1BD11BF0u);  FADDC(x1, x1, 2u);
    x0 = fadd(x0, x1, one);  x1 = rotl32(x1, 13) ^ x0;
    x0 = fadd(x0, x1, one);  x1 = rotl32(x1, 15) ^ x0;
    x0 = fadd(x0, x1, one);  x1 = rotl32(x1, 26) ^ x0;
    x0 = fadd(x0, x1, one);  x1 = rotl32(x1,  6) ^ x0;
    /* x0 += ks0 (=0) */     FADDC(x1, x1, 45u);
    x0 = fadd(x0, x1, one);  x1 = rotl32(x1, 17) ^ x0;
    x0 = fadd(x0, x1, one);  x1 = rotl32(x1, 29) ^ x0;
    x0 = fadd(x0, x1, one);  x1 = rotl32(x1, 16) ^ x0;
    x0 = fadd(x0, x1, one);  x1 = rotl32(x1, 24) ^ x0;
    FADDC(x0, x0, 42u);  FADDC(x1, x1, 0x1BD11BF0u + 4u);
    x0 = fadd(x0, x1, one);  x1 = rotl32(x1, 13) ^ x0;
    x0 = fadd(x0, x1, one);  x1 = rotl32(x1, 15) ^ x0;
    x0 = fadd(x0, x1, one);  x1 = rotl32(x1, 26) ^ x0;
    x0 = fadd(x0, x1, one);  x1 = rotl32(x1,  6) ^ x0;
    FADDC(x0, x0, 0x1BD11BF0u);  FADDC(x1, x1, 5u);
    return x0 ^ x1;
}

__global__ __launch_bounds__(256)
void dnm_kernel(const float4* __restrict__ embeds,
                const float* __restrict__ factors,
                const float4* __restrict__ mask_token,
                float4* __restrict__ out_embeds,
                float4* __restrict__ out_mask,
                uint32_t one) {
    // 9-padded histogram: bin b lives at b + (b>>3). For loads h[lane*9+t],
    // 9 is odd -> lane*9 mod 32 is a bijection -> conflict-free for every t.
    __shared__ uint32_t sh_hist[288];
    __shared__ unsigned long long sh_cand[1040];   // unique keys (m<<10)|col
    __shared__ int sh_cnt;
    __shared__ uint32_t sh_thrM;
    __shared__ uint32_t sh_thrC;
    __shared__ uint32_t sh_thrFast;  // (thrM<<9)|511 if thrM unique, else 0

    const int row = blockIdx.x;
    const int tid = threadIdx.x;
    const int lane = tid & 31;
    const uint32_t M8  = one << 8;   // umulhi(x,M8)  == x>>24 (fma pipe)
    const uint32_t M29 = one << 29;  // umulhi(x,M29) == x>>3  (fma pipe)

    // Early register prefetch (empirically best placement).
    const float4 e  = embeds[(size_t)row * (NE / 4) + tid];
    const float4 mt = __ldg(&mask_token[tid]);

    // k computed by all threads (same-address LDG -> broadcast).
    const float f = __ldg(&factors[row]);
    int ktmp = (int)floorf(307.2f * f);   // f32(1024*0.3)*factor, floor
    const uint32_t k = (uint32_t)(ktmp < 1 ? 1 : ktmp);

    sh_hist[tid] = 0u;
    if (tid < 32) sh_hist[256 + tid] = 0u;
    if (tid == 0) sh_cnt = 0;
    __syncthreads();                                         // barrier 1

    // ---- Phase 1: RNG for 4 contiguous columns + fused padded histogram --
    // Rank order = (bits>>9) asc, ties by column asc (stable argsort).
    uint32_t bits[4];
    const uint32_t base = (uint32_t)(row * NE + tid * 4) + 42u;  // +ks1 baked in
    #pragma unroll
    for (int j = 0; j < 4; j++) {
        bits[j] = tf(base + j, one);
        const uint32_t bin = __umulhi(bits[j], M8);          // bits>>24
        atomicAdd(&sh_hist[bin + __umulhi(bin, M29)], 1u);   // padded index
    }
    __syncthreads();                                         // barrier 2

    // ---- Phase 2: EVERY warp scans its padded bins (conflict-free) -------
    // Result (bkt, rem) stays in registers; no barrier needed before phase 3.
    uint32_t bkt, rem;
    {
        uint32_t v[8];
        uint32_t s = 0;
        const int b9 = lane * 9;
        #pragma unroll
        for (int t = 0; t < 8; t++) { v[t] = sh_hist[b9 + t]; s += v[t]; }
        uint32_t incl = s;
        #pragma unroll
        for (int o = 1; o < 32; o <<= 1) {
            uint32_t n = __shfl_up_sync(0xFFFFFFFFu, incl, o);
            if (lane >= o) incl += n;
        }
        const uint32_t excl = incl - s;
        uint32_t mybkt = 0, myrem = 0;
        const bool hit = (excl < k && k <= incl);            // unique lane
        if (hit) {
            uint32_t c = excl;
            #pragma unroll
            for (int t = 0; t < 8; t++) {
                if (k <= c + v[t]) { mybkt = (uint32_t)(lane * 8 + t); myrem = k - c; break; }
                c += v[t];
            }
        }
        const unsigned bal = __ballot_sync(0xFFFFFFFFu, hit);
        const int src = __ffs(bal) - 1;
        bkt = __shfl_sync(0xFFFFFFFFu, mybkt, src);
        rem = __shfl_sync(0xFFFFFFFFu, myrem, src);
    }

    // ---- Phase 3: collect boundary-bucket candidates as unique keys ------
    #pragma unroll
    for (int j = 0; j < 4; j++) {
        if (__umulhi(bits[j], M8) == bkt) {               // bits>>24 on fma pipe
            const int p = atomicAdd(&sh_cnt, 1);
            sh_cand[p] = ((unsigned long long)(bits[j] >> 9) << 10)
                         | (unsigned)(tid * 4 + j);
        }
    }
    __syncthreads();                                         // barrier 3

    // ---- Phase 4: warp 0 ranks candidates; uniq folded into same loop ----
    if (tid < 32) {
        const int c = sh_cnt;
        for (int idx = lane; idx < c; idx += 32) {
            const unsigned long long key = sh_cand[idx];
            const uint32_t mi = (uint32_t)(key >> 10);
            int rank = 0, eq = 0;
            for (int j2 = 0; j2 < c; j2++) {
                const unsigned long long kj = sh_cand[j2];
                rank += (kj < key);
                eq   += ((uint32_t)(kj >> 10) == mi);   // counts self
            }
            if (rank == (int)rem - 1) {                  // unique winner lane
                sh_thrM = mi;
                sh_thrC = (uint32_t)key & 1023u;
                sh_thrFast = (eq == 1) ? ((mi << 9) | 511u) : 0u;
            }
        }
    }
    __syncthreads();                                         // barrier 4

    // ---- Phase 5: apply mask -------------------------------------------
    bool k0, k1, k2, k3;
    const uint32_t tF = sh_thrFast;
    if (tF) {
        // thrM unique in row: masked <=> bits <= (thrM<<9)|511
        k0 = bits[0] <= tF;
        k1 = bits[1] <= tF;
        k2 = bits[2] <= tF;
        k3 = bits[3] <= tF;
    } else {
        // rare (~5 rows / 32768): exact lexicographic tie-break by column
        const uint32_t thrM = sh_thrM;
        const uint32_t thrC = sh_thrC;
        const uint32_t cbase = (uint32_t)(tid * 4);
        const uint32_t m0 = bits[0] >> 9, m1 = bits[1] >> 9;
        const uint32_t m2 = bits[2] >> 9, m3 = bits[3] >> 9;
        k0 = (m0 < thrM) || ((m0 == thrM) && (cbase + 0 <= thrC));
        k1 = (m1 < thrM) || ((m1 == thrM) && (cbase + 1 <= thrC));
        k2 = (m2 < thrM) || ((m2 == thrM) && (cbase + 2 <= thrC));
        k3 = (m3 < thrM) || ((m3 == thrM) && (cbase + 3 <= thrC));
    }

    float4 oe, om;
    oe.x = k0 ? mt.x : e.x;  om.x = k0 ? 0.0f : 1.0f;
    oe.y = k1 ? mt.y : e.y;  om.y = k1 ? 0.0f : 1.0f;
    oe.z = k2 ? mt.z : e.z;  om.z = k2 ? 0.0f : 1.0f;
    oe.w = k3 ? mt.w : e.w;  om.w = k3 ? 0.0f : 1.0f;

    out_embeds[(size_t)row * (NE / 4) + tid] = oe;
    out_mask[(size_t)row * (NE / 4) + tid]   = om;
}

extern "C" void kernel_launch(void* const* d_in, const int* in_sizes, int n_in,
                              void* d_out, int out_size) {
    const float4* embeds = (const float4*)d_in[0];     // [32768, 1024] f32
    const float* factors = (const float*)d_in[1];      // [32768] f32
    const float4* mask_token = (const float4*)d_in[2]; // [1, 1024] f32

    float* out = (float*)d_out;
    float4* out_embeds = (float4*)out;                       // [B, E]
    float4* out_mask = (float4*)(out + (size_t)NB * NE);     // [B, E]

    dnm_kernel<<<NB, 256>>>(embeds, factors, mask_token, out_embeds, out_mask, 1u);
}

// round 17
// speedup vs baseline: 1.1485x; 1.1485x over previous
#include <cuda_runtime.h>
#include <stdint.h>

#define NB 32768
#define NE 1024

// add on the FMA pipe: d = a*one + b (one==1, opaque runtime value -> IMAD)
static __device__ __forceinline__ uint32_t fadd(uint32_t a, uint32_t b, uint32_t one) {
    uint32_t d;
    asm("mad.lo.u32 %0, %1, %2, %3;" : "=r"(d) : "r"(a), "r"(one), "r"(b));
    return d;
}
#define FADDC(d, a, C) asm("mad.lo.u32 %0, %1, %2, %3;" : "=r"(d) : "r"(a), "r"(one), "n"(C))

static __device__ __forceinline__ uint32_t rotl32(uint32_t x, int r) {
    return __funnelshift_l(x, x, r);
}

// threefry2x32, key (0,42), block (0,i). Returns x0^x1 after 20 rounds —
// matches jax _threefry_random_bits_partitionable (bit_width=32).
// Caller pre-adds ks1=42 into x1. Adds forced to IMAD (fma pipe);
// rotates stay SHF+LOP3 (alu pipe) — empirically the fastest form.
static __device__ __forceinline__ uint32_t tf(uint32_t x1, uint32_t one) {
    uint32_t x0;
    x0 = x1;                 x1 = rotl32(x1, 13) ^ x0;
    x0 = fadd(x0, x1, one);  x1 = rotl32(x1, 15) ^ x0;
    x0 = fadd(x0, x1, one);  x1 = rotl32(x1, 26) ^ x0;
    x0 = fadd(x0, x1, one);  x1 = rotl32(x1,  6) ^ x0;
    FADDC(x0, x0, 42u);  FADDC(x1, x1, 0x1BD11BF0u + 1u);
    x0 = fadd(x0, x1, one);  x1 = rotl32(x1, 17) ^ x0;
    x0 = fadd(x0, x1, one);  x1 = rotl32(x1, 29) ^ x0;
    x0 = fadd(x0, x1, one);  x1 = rotl32(x1, 16) ^ x0;
    x0 = fadd(x0, x1, one);  x1 = rotl32(x1, 24) ^ x0;
    FADDC(x0, x0, 0x1BD11BF0u);  FADDC(x1, x1, 2u);
    x0 = fadd(x0, x1, one);  x1 = rotl32(x1, 13) ^ x0;
    x0 = fadd(x0, x1, one);  x1 = rotl32(x1, 15) ^ x0;
    x0 = fadd(x0, x1, one);  x1 = rotl32(x1, 26) ^ x0;
    x0 = fadd(x0, x1, one);  x1 = rotl32(x1,  6) ^ x0;
    /* x0 += ks0 (=0) */     FADDC(x1, x1, 45u);
    x0 = fadd(x0, x1, one);  x1 = rotl32(x1, 17) ^ x0;
    x0 = fadd(x0, x1, one);  x1 = rotl32(x1, 29) ^ x0;
    x0 = fadd(x0, x1, one);  x1 = rotl32(x1, 16) ^ x0;
    x0 = fadd(x0, x1, one);  x1 = rotl32(x1, 24) ^ x0;
    FADDC(x0, x0, 42u);  FADDC(x1, x1, 0x1BD11BF0u + 4u);
    x0 = fadd(x0, x1, one);  x1 = rotl32(x1, 13) ^ x0;
    x0 = fadd(x0, x1, one);  x1 = rotl32(x1, 15) ^ x0;
    x0 = fadd(x0, x1, one);  x1 = rotl32(x1, 26) ^ x0;
    x0 = fadd(x0, x1, one);  x1 = rotl32(x1,  6) ^ x0;
    FADDC(x0, x0, 0x1BD11BF0u);  FADDC(x1, x1, 5u);
    return x0 ^ x1;
}

__global__ __launch_bounds__(256)
void dnm_kernel(const float4* __restrict__ embeds,
                const float* __restrict__ factors,
                const float4* __restrict__ mask_token,
                float4* __restrict__ out_embeds,
                float4* __restrict__ out_mask,
                uint32_t one) {
    __shared__ uint32_t sh_hist[256];
    __shared__ unsigned long long sh_cand[1040];   // unique keys (m<<10)|col
    __shared__ int sh_cnt;
    __shared__ int sh_k;
    __shared__ int sh_bucket;
    __shared__ int sh_rem;
    __shared__ uint32_t sh_thrM;
    __shared__ uint32_t sh_thrC;
    __shared__ uint32_t sh_thrFast;  // (thrM<<9)|511 if thrM unique, else 0

    const int row = blockIdx.x;
    const int tid = threadIdx.x;
    const uint32_t M8 = one << 8;    // opaque: umulhi(x,M8) == x>>24 (fma pipe)

    // Early register prefetch (empirically best placement).
    const float4 e  = embeds[(size_t)row * (NE / 4) + tid];
    const float4 mt = __ldg(&mask_token[tid]);

    sh_hist[tid] = 0u;
    if (tid == 0) {
        sh_cnt = 0;
        const float f = __ldg(&factors[row]);
        int k = (int)floorf(307.2f * f);   // f32(1024*0.3)*factor, floor
        sh_k = k < 1 ? 1 : k;
    }
    __syncthreads();

    // ---- Phase 1: RNG for 4 contiguous columns + fused histogram ---------
    // Rank order = (bits>>9) asc, ties by column asc (stable argsort).
    uint32_t bits[4];
    const uint32_t base = (uint32_t)(row * NE + tid * 4) + 42u;  // +ks1 baked in
    #pragma unroll
    for (int j = 0; j < 4; j++) {
        bits[j] = tf(base + j, one);
        atomicAdd(&sh_hist[__umulhi(bits[j], M8)], 1u);   // bucket = bits>>24
    }
    __syncthreads();

    // ---- Phase 2: warp 0 scans 256 bins for the k-th-smallest bucket -----
    if (tid < 32) {
        const int lane = tid;
        uint32_t v[8];
        uint32_t s = 0;
        #pragma unroll
        for (int t = 0; t < 8; t++) { v[t] = sh_hist[lane * 8 + t]; s += v[t]; }
        uint32_t incl = s;
        #pragma unroll
        for (int o = 1; o < 32; o <<= 1) {
            uint32_t n = __shfl_up_sync(0xFFFFFFFFu, incl, o);
            if (lane >= o) incl += n;
        }
        const uint32_t excl = incl - s;
        const uint32_t k = (uint32_t)sh_k;
        if (excl < k && k <= incl) {            // unique lane
            uint32_t c = excl;
            #pragma unroll
            for (int t = 0; t < 8; t++) {
                if (k <= c + v[t]) { sh_bucket = lane * 8 + t; sh_rem = (int)(k - c); break; }
                c += v[t];
            }
        }
    }
    __syncthreads();

    // ---- Phase 3: collect boundary-bucket candidates as unique keys ------
    const uint32_t bkt = (uint32_t)sh_bucket;
    #pragma unroll
    for (int j = 0; j < 4; j++) {
        if (__umulhi(bits[j], M8) == bkt) {               // bits>>24 on fma pipe
            const int p = atomicAdd(&sh_cnt, 1);
            sh_cand[p] = ((unsigned long long)(bits[j] >> 9) << 10)
                         | (unsigned)(tid * 4 + j);
        }
    }
    __syncthreads();

    // ---- Phase 4: warp 0 ranks candidates; uniq folded into same loop ----
    if (tid < 32) {
        const int c = sh_cnt;
        const int rem = sh_rem;
        for (int idx = tid; idx < c; idx += 32) {
            const unsigned long long key = sh_cand[idx];
            const uint32_t mi = (uint32_t)(key >> 10);
            int rank = 0, eq = 0;
            for (int j2 = 0; j2 < c; j2++) {
                const unsigned long long kj = sh_cand[j2];
                rank += (kj < key);
                eq   += ((uint32_t)(kj >> 10) == mi);   // counts self
            }
            if (rank == rem - 1) {                       // unique winner lane
                sh_thrM = mi;
                sh_thrC = (uint32_t)key & 1023u;
                sh_thrFast = (eq == 1) ? ((mi << 9) | 511u) : 0u;
            }
        }
    }
    __syncthreads();

    // ---- Phase 5: apply mask -------------------------------------------
    bool k0, k1, k2, k3;
    const uint32_t tF = sh_thrFast;
    if (tF) {
        // thrM unique in row: masked <=> bits <= (thrM<<9)|511
        k0 = bits[0] <= tF;
        k1 = bits[1] <= tF;
        k2 = bits[2] <= tF;
        k3 = bits[3] <= tF;
    } else {
        // rare (~5 rows / 32768): exact lexicographic tie-break by column
        const uint32_t thrM = sh_thrM;
        const uint32_t thrC = sh_thrC;
        const uint32_t cbase = (uint32_t)(tid * 4);
        const uint32_t m0 = bits[0] >> 9, m1 = bits[1] >> 9;
        const uint32_t m2 = bits[2] >> 9, m3 = bits[3] >> 9;
        k0 = (m0 < thrM) || ((m0 == thrM) && (cbase + 0 <= thrC));
        k1 = (m1 < thrM) || ((m1 == thrM) && (cbase + 1 <= thrC));
        k2 = (m2 < thrM) || ((m2 == thrM) && (cbase + 2 <= thrC));
        k3 = (m3 < thrM) || ((m3 == thrM) && (cbase + 3 <= thrC));
    }

    float4 oe, om;
    oe.x = k0 ? mt.x : e.x;  om.x = k0 ? 0.0f : 1.0f;
    oe.y = k1 ? mt.y : e.y;  om.y = k1 ? 0.0f : 1.0f;
    oe.z = k2 ? mt.z : e.z;  om.z = k2 ? 0.0f : 1.0f;
    oe.w = k3 ? mt.w : e.w;  om.w = k3 ? 0.0f : 1.0f;

    out_embeds[(size_t)row * (NE / 4) + tid] = oe;
    out_mask[(size_t)row * (NE / 4) + tid]   = om;
}

extern "C" void kernel_launch(void* const* d_in, const int* in_sizes, int n_in,
                              void* d_out, int out_size) {
    const float4* embeds = (const float4*)d_in[0];     // [32768, 1024] f32
    const float* factors = (const float*)d_in[1];      // [32768] f32
    const float4* mask_token = (const float4*)d_in[2]; // [1, 1024] f32

    float* out = (float*)d_out;
    float4* out_embeds = (float4*)out;                       // [B, E]
    float4* out_mask = (float4*)(out + (size_t)NB * NE);     // [B, E]

    dnm_kernel<<<NB, 256>>>(embeds, factors, mask_token, out_embeds, out_mask, 1u);
}